// round 15
// baseline (speedup 1.0000x reference)
#include <cuda_runtime.h>
#include <cuda_fp16.h>
#include <cstdint>
#include <cstddef>

#define B_ 16
#define L_ 16384
#define C_ 256
#define NH 8
#define FFN 512
#define EPS 1e-5f
#define SCALE_ATT 0.17677669529663687f
#define JOBS 2048

// k1 smem byte offsets
#define O_A   0         /* A fp16 double buffer: 2 x 10240 */
#define O_B   20480     /* B fp16 quad buffer: 4 x 20480 -> 102400 */
#define O_MSM 0         /* m^ fp16 [128][264] = 67584, overlays GEMM bufs */
#define O_SPC 102400    /* score MMA partials [2][128][8] = 8192 */
#define O_ST  110592    /* row sum partials [128][4] = 2048 */
#define O_QS  112640    /* row sumsq partials [128][4] = 2048 */
#define O_WH  114688    /* w~ fp16 [8][136] = 2176 (+pad) */
#define O_GQ  117056    /* gq fp16 [8][264] = 4224 */
#define O_IOR 121280    /* [8][128] float = 4096 */
#define O_SC  125376    /* scores float [8][128] = 4096 */
#define O_MU  129472    /* 128 floats */
#define O_RS  129984    /* 128 floats */
#define O_CG  130496
#define O_CQC 130528
#define O_CS2 130560
#define O_CW  130592
#define O_BIP 130624
#define O_GIP 131648
#define O_BEI 132672
#define SM1   133696

__device__ __half g_gqh[B_ * NH * C_];
__device__ float g_G[B_ * NH];
__device__ float g_qc[B_ * NH];
__device__ float g_pmax[JOBS * NH];
__device__ float g_psum[JOBS * NH];
__device__ float g_pctx[(size_t)JOBS * NH * C_];
__device__ float g_ctxn[B_ * NH * C_];
__device__ float g_pref[4];
__device__ __align__(16) __half g_wh[C_ * C_];   // W_ip^T fp16, n-major

__device__ __forceinline__ uint32_t smem_u32(const void* p) {
    uint32_t a;
    asm("{ .reg .u64 t; cvta.to.shared.u64 t, %1; cvt.u32.u64 %0, t; }" : "=r"(a) : "l"(p));
    return a;
}
__device__ __forceinline__ void ldmx4(uint32_t* r, uint32_t a) {
    asm volatile("ldmatrix.sync.aligned.m8n8.x4.shared.b16 {%0,%1,%2,%3}, [%4];"
        : "=r"(r[0]), "=r"(r[1]), "=r"(r[2]), "=r"(r[3]) : "r"(a));
}
__device__ __forceinline__ void ldmx4t(uint32_t* r, uint32_t a) {
    asm volatile("ldmatrix.sync.aligned.m8n8.x4.trans.shared.b16 {%0,%1,%2,%3}, [%4];"
        : "=r"(r[0]), "=r"(r[1]), "=r"(r[2]), "=r"(r[3]) : "r"(a));
}
__device__ __forceinline__ void ldmx2(uint32_t* r, uint32_t a) {
    asm volatile("ldmatrix.sync.aligned.m8n8.x2.shared.b16 {%0,%1}, [%2];"
        : "=r"(r[0]), "=r"(r[1]) : "r"(a));
}
__device__ __forceinline__ void mma16816(float* d, const uint32_t* a, uint32_t b0, uint32_t b1) {
    asm volatile("mma.sync.aligned.m16n8k16.row.col.f32.f16.f16.f32 "
        "{%0,%1,%2,%3}, {%4,%5,%6,%7}, {%8,%9}, {%0,%1,%2,%3};"
        : "+f"(d[0]), "+f"(d[1]), "+f"(d[2]), "+f"(d[3])
        : "r"(a[0]), "r"(a[1]), "r"(a[2]), "r"(a[3]), "r"(b0), "r"(b1));
}
#define CPA(dst, src) asm volatile("cp.async.cg.shared.global [%0], [%1], 16;" :: "r"(dst), "l"(src))
#define CPC() asm volatile("cp.async.commit_group;" ::: "memory")
#define CPW(n) asm volatile("cp.async.wait_group %0;" :: "n"(n) : "memory")

// ---- K0 fused: blocks 0-15 = query fold; blocks 16-79 = W_ip^T transpose ----
__global__ void __launch_bounds__(1024) k0f(
    const float* __restrict__ query, const float* __restrict__ W_q,
    const float* __restrict__ b_q, const float* __restrict__ W_kv,
    const float* __restrict__ b_kv, const float* __restrict__ g_q,
    const float* __restrict__ be_q, const float* __restrict__ g_ip,
    const float* __restrict__ be_ip, const float* __restrict__ W_ip) {
    const int t = threadIdx.x, lane = t & 31, wid = t >> 5;

    if (blockIdx.x >= B_) {   // ---- transpose W_ip -> g_wh fp16 ----
        __shared__ float tile[32][33];
        const int bi = blockIdx.x - B_;
        const int bx = bi & 7, by = bi >> 3;
        const int tx = lane, ty = wid;
        tile[ty][tx] = W_ip[(by * 32 + ty) * C_ + bx * 32 + tx];
        __syncthreads();
        g_wh[(bx * 32 + ty) * C_ + by * 32 + tx] = __float2half_rn(tile[tx][ty]);
        return;
    }

    __shared__ float qn[C_], qs[C_], part[4 * C_], red[8], red2[8];
    __shared__ float wG[32 * 8], wQ[32 * 8];
    const int b = blockIdx.x;

    if (t < C_) {
        float x = query[b * C_ + t];
        float s = x, s2 = x * x;
        #pragma unroll
        for (int o = 16; o >= 1; o >>= 1) {
            s += __shfl_xor_sync(~0u, s, o);
            s2 += __shfl_xor_sync(~0u, s2, o);
        }
        if (lane == 0) { red[wid] = s; red2[wid] = s2; }
    }
    __syncthreads();
    if (t < C_) {
        float su = 0.f, sq = 0.f;
        #pragma unroll
        for (int i = 0; i < 8; i++) { su += red[i]; sq += red2[i]; }
        float mean = su / C_, var = sq / C_ - mean * mean, rs = rsqrtf(var + EPS);
        qn[t] = (query[b * C_ + t] - mean) * rs * g_q[t] + be_q[t];
    }
    __syncthreads();
    {
        const int tt = t & 255, sl = t >> 8;
        const float* W = W_q + tt;
        float a0 = 0.f, a1 = 0.f, a2 = 0.f, a3 = 0.f;
        const int c0 = sl * 64;
        #pragma unroll 4
        for (int c = 0; c < 64; c += 4) {
            a0 += qn[c0 + c] * W[(size_t)(c0 + c) * C_];
            a1 += qn[c0 + c + 1] * W[(size_t)(c0 + c + 1) * C_];
            a2 += qn[c0 + c + 2] * W[(size_t)(c0 + c + 2) * C_];
            a3 += qn[c0 + c + 3] * W[(size_t)(c0 + c + 3) * C_];
        }
        part[sl * C_ + tt] = (a0 + a1) + (a2 + a3);
    }
    __syncthreads();
    if (t < C_)
        qs[t] = b_q[t] + ((part[t] + part[C_ + t]) + (part[2 * C_ + t] + part[3 * C_ + t]));
    __syncthreads();
    {
        float gAcc = 0.f, qAcc = 0.f;
        for (int i = 0; i < 8; i++) {
            const int c = wid * 8 + i;
            const float* wr = W_kv + (size_t)c * (2 * C_);
            float accs[8];
            #pragma unroll
            for (int h = 0; h < NH; h++)
                accs[h] = wr[h * 32 + lane] * qs[h * 32 + lane];
            #pragma unroll
            for (int h = 0; h < NH; h++) {
                float v = accs[h];
                #pragma unroll
                for (int o = 16; o >= 1; o >>= 1) v += __shfl_xor_sync(~0u, v, o);
                if (lane == h) {
                    float a = v * SCALE_ATT;
                    __half gh = __float2half_rn(a * g_ip[c]);
                    g_gqh[(b * NH + h) * C_ + c] = gh;
                    gAcc += __half2float(gh);
                    qAcc += a * be_ip[c];
                }
            }
        }
        if (lane < NH) { wG[wid * 8 + lane] = gAcc; wQ[wid * 8 + lane] = qAcc; }
    }
    __syncthreads();
    if (t < NH) {
        float G = 0.f, Q = 0.f;
        #pragma unroll 8
        for (int w = 0; w < 32; w++) { G += wG[w * 8 + t]; Q += wQ[w * 8 + t]; }
        float qb = 0.f;
        #pragma unroll 8
        for (int d = 0; d < 32; d++) qb += qs[t * 32 + d] * b_kv[t * 32 + d];
        g_G[b * NH + t] = G;
        g_qc[b * NH + t] = Q + qb * SCALE_ATT;
    }
}

// ---- K1: fp16 HMMA fused kernel, single-barrier pipelined GEMM ----
__global__ void __launch_bounds__(512, 1)
k1(const float* __restrict__ mem, const float* __restrict__ ior,
   const float* __restrict__ b_ip, const float* __restrict__ g_ip,
   const float* __restrict__ be_ip) {
    extern __shared__ char sm[];
    float* S = (float*)sm;
    const uint32_t smb = smem_u32(sm);
    const int t = threadIdx.x, lane = t & 31, wid = t >> 5;
    const int rg = wid >> 2, cg = wid & 3;    // 4x4 warp grid
    const int j = blockIdx.x, b = j >> 7, row0 = (j & 127) << 7;

    for (int i = t; i < NH * C_; i += 512)
        *(__half*)(sm + O_GQ + (((i >> 8) * 264 + (i & 255)) * 2)) = g_gqh[b * NH * C_ + i];
    if (t < NH) {
        S[(O_CG >> 2) + t] = g_G[b * NH + t];
        S[(O_CQC >> 2) + t] = g_qc[b * NH + t];
    }
    for (int i = t; i < NH * 128; i += 512)
        S[(O_IOR >> 2) + i] = ior[(size_t)(b * NH + (i >> 7)) * L_ + row0 + (i & 127)];
    if (t < C_) {
        S[(O_BIP >> 2) + t] = b_ip[t];
        S[(O_GIP >> 2) + t] = g_ip[t];
        S[(O_BEI >> 2) + t] = be_ip[t];
    }

    const float4* mem4 = (const float4*)mem;
    const int ar = t >> 2, aq = t & 3;
    const size_t abase = (size_t)(b * L_ + row0 + ar) * 64;
    float4 av0 = mem4[abase + aq * 2], av1 = mem4[abase + aq * 2 + 1];

    const int bn = t >> 1, bf = t & 1;
    #pragma unroll
    for (int pk = 0; pk < 2; pk++) {
        const char* sH = (const char*)g_wh + ((size_t)bn * 256 + pk * 32 + bf * 16) * 2;
        uint32_t d0 = smb + O_B + pk * 20480 + bn * 80 + bf * 32;
        CPA(d0, sH); CPA(d0 + 16, sH + 16);
        CPC();
    }

    float d[16][4];
    #pragma unroll
    for (int i = 0; i < 16; i++)
        #pragma unroll
        for (int q = 0; q < 4; q++) d[i][q] = 0.f;

    const int lg = lane >> 3, lr = lane & 7;
    const uint32_t aOff = (rg * 32 + ((lg & 1) << 3) + lr) * 80 + (lg >> 1) * 16;
    const uint32_t bOff = (cg * 64 + ((lg >> 1) << 3) + lr) * 80 + (lg & 1) * 16;

    for (int kc = 0; kc < 8; kc++) {
        {
            __half2 h0 = __floats2half2_rn(av0.x, av0.y);
            __half2 h1 = __floats2half2_rn(av0.z, av0.w);
            __half2 h2 = __floats2half2_rn(av1.x, av1.y);
            __half2 h3 = __floats2half2_rn(av1.z, av1.w);
            *(uint4*)(sm + O_A + (kc & 1) * 10240 + ar * 80 + aq * 16) =
                make_uint4(*(uint32_t*)&h0, *(uint32_t*)&h1, *(uint32_t*)&h2, *(uint32_t*)&h3);
        }
        if (kc < 7) {
            av0 = mem4[abase + (kc + 1) * 8 + aq * 2];
            av1 = mem4[abase + (kc + 1) * 8 + aq * 2 + 1];
        }
        if (kc < 6) {
            const char* sH = (const char*)g_wh + ((size_t)bn * 256 + (kc + 2) * 32 + bf * 16) * 2;
            uint32_t d0 = smb + O_B + ((kc + 2) & 3) * 20480 + bn * 80 + bf * 32;
            CPA(d0, sH); CPA(d0 + 16, sH + 16);
            CPC();
            CPW(2);
        } else if (kc == 6) {
            CPW(1);
        } else {
            CPW(0);
        }
        __syncthreads();

        const uint32_t aAddr = smb + O_A + (kc & 1) * 10240 + aOff;
        const uint32_t bufB = smb + O_B + (kc & 3) * 20480 + bOff;
        #pragma unroll
        for (int ks = 0; ks < 2; ks++) {
            uint32_t a[2][4];
            ldmx4(a[0], aAddr + ks * 32);
            ldmx4(a[1], aAddr + 1280 + ks * 32);
            uint32_t bh[4][4];
            #pragma unroll
            for (int jt = 0; jt < 4; jt++)
                ldmx4(bh[jt], bufB + jt * 1280 + ks * 32);
            #pragma unroll
            for (int mi = 0; mi < 2; mi++)
                #pragma unroll
                for (int jt = 0; jt < 4; jt++) {
                    mma16816(d[mi * 8 + 2 * jt], a[mi], bh[jt][0], bh[jt][1]);
                    mma16816(d[mi * 8 + 2 * jt + 1], a[mi], bh[jt][2], bh[jt][3]);
                }
        }
    }
    __syncthreads();

    const int cq = (lane & 3) * 2;
    #pragma unroll
    for (int mi = 0; mi < 2; mi++) {
        int rA = rg * 32 + mi * 16 + (lane >> 2), rB = rA + 8;
        float sA = 0.f, qA = 0.f, sB = 0.f, qB = 0.f;
        #pragma unroll
        for (int nj = 0; nj < 8; nj++) {
            int c = cg * 64 + (nj >> 1) * 16 + (nj & 1) * 8 + cq;
            float2 bb = *(float2*)&S[(O_BIP >> 2) + c];
            float* dd = d[mi * 8 + nj];
            float x0 = fmaxf(dd[0] + bb.x, 0.f), x1 = fmaxf(dd[1] + bb.y, 0.f);
            float y0 = fmaxf(dd[2] + bb.x, 0.f), y1 = fmaxf(dd[3] + bb.y, 0.f);
            sA += x0 + x1; qA += x0 * x0 + x1 * x1;
            sB += y0 + y1; qB += y0 * y0 + y1 * y1;
            *(__half2*)(sm + O_MSM + (rA * 264 + c) * 2) = __floats2half2_rn(x0, x1);
            *(__half2*)(sm + O_MSM + (rB * 264 + c) * 2) = __floats2half2_rn(y0, y1);
        }
        #pragma unroll
        for (int o = 1; o <= 2; o <<= 1) {
            sA += __shfl_xor_sync(~0u, sA, o); qA += __shfl_xor_sync(~0u, qA, o);
            sB += __shfl_xor_sync(~0u, sB, o); qB += __shfl_xor_sync(~0u, qB, o);
        }
        if ((lane & 3) == 0) {
            S[(O_ST >> 2) + rA * 4 + cg] = sA; S[(O_QS >> 2) + rA * 4 + cg] = qA;
            S[(O_ST >> 2) + rB * 4 + cg] = sB; S[(O_QS >> 2) + rB * 4 + cg] = qB;
        }
    }
    __syncthreads();

    {
        const int mt = wid & 7, khalf = wid >> 3;
        float dS[4] = {0.f, 0.f, 0.f, 0.f};
        uint32_t aA = smb + O_MSM + ((mt * 16 + ((lg & 1) << 3) + lr) * 264 + (lg >> 1) * 8) * 2;
        uint32_t bA = smb + O_GQ + ((lane & 7) * 264 + ((lane >> 3) & 1) * 8) * 2;
        #pragma unroll
        for (int kk = 0; kk < 8; kk++) {
            int k = khalf * 128 + kk * 16;
            uint32_t a[4], bb[2];
            ldmx4(a, aA + k * 2);
            ldmx2(bb, bA + k * 2);
            mma16816(dS, a, bb[0], bb[1]);
        }
        int r = mt * 16 + (lane >> 2), h0 = (lane & 3) * 2;
        *(float2*)&S[(O_SPC >> 2) + khalf * 1024 + r * 8 + h0] = make_float2(dS[0], dS[1]);
        *(float2*)&S[(O_SPC >> 2) + khalf * 1024 + (r + 8) * 8 + h0] = make_float2(dS[2], dS[3]);
    }
    __syncthreads();

    for (int e = t; e < NH * 128; e += 512) {
        int h = e >> 7, rr = e & 127;
        float P = S[(O_SPC >> 2) + rr * 8 + h] + S[(O_SPC >> 2) + 1024 + rr * 8 + h];
        const float* st = S + (O_ST >> 2) + rr * 4;
        const float* sqp = S + (O_QS >> 2) + rr * 4;
        float su = (st[0] + st[1]) + (st[2] + st[3]);
        float sq = (sqp[0] + sqp[1]) + (sqp[2] + sqp[3]);
        float mu = su * (1.f / C_);
        float rs = rsqrtf(sq * (1.f / C_) - mu * mu + EPS);
        if (h == 0) { S[(O_MU >> 2) + rr] = mu; S[(O_RS >> 2) + rr] = rs; }
        S[(O_SC >> 2) + e] = (rs * (P - mu * S[(O_CG >> 2) + h]) + S[(O_CQC >> 2) + h])
                             * S[(O_IOR >> 2) + e];
    }
    __syncthreads();

    if (wid < NH) {
        float v0 = S[(O_SC >> 2) + wid * 128 + lane];
        float v1 = S[(O_SC >> 2) + wid * 128 + 32 + lane];
        float v2 = S[(O_SC >> 2) + wid * 128 + 64 + lane];
        float v3 = S[(O_SC >> 2) + wid * 128 + 96 + lane];
        float mx = fmaxf(fmaxf(v0, v1), fmaxf(v2, v3));
        #pragma unroll
        for (int o = 16; o >= 1; o >>= 1) mx = fmaxf(mx, __shfl_xor_sync(~0u, mx, o));
        float e0 = __expf(v0 - mx), e1 = __expf(v1 - mx);
        float e2 = __expf(v2 - mx), e3 = __expf(v3 - mx);
        float rs0 = S[(O_RS >> 2) + lane],      mu0 = S[(O_MU >> 2) + lane];
        float rs1 = S[(O_RS >> 2) + 32 + lane], mu1 = S[(O_MU >> 2) + 32 + lane];
        float rs2 = S[(O_RS >> 2) + 64 + lane], mu2 = S[(O_MU >> 2) + 64 + lane];
        float rs3 = S[(O_RS >> 2) + 96 + lane], mu3 = S[(O_MU >> 2) + 96 + lane];
        float w0 = e0 * rs0, w1 = e1 * rs1, w2 = e2 * rs2, w3 = e3 * rs3;
        *(__half*)(sm + O_WH + (wid * 136 + lane) * 2) = __float2half_rn(w0);
        *(__half*)(sm + O_WH + (wid * 136 + 32 + lane) * 2) = __float2half_rn(w1);
        *(__half*)(sm + O_WH + (wid * 136 + 64 + lane) * 2) = __float2half_rn(w2);
        *(__half*)(sm + O_WH + (wid * 136 + 96 + lane) * 2) = __float2half_rn(w3);
        float es = (e0 + e1) + (e2 + e3);
        float s2 = w0 * mu0 + w1 * mu1 + w2 * mu2 + w3 * mu3;
        #pragma unroll
        for (int o = 16; o >= 1; o >>= 1) {
            es += __shfl_xor_sync(~0u, es, o);
            s2 += __shfl_xor_sync(~0u, s2, o);
        }
        if (lane == 0) {
            g_pmax[j * NH + wid] = mx;
            g_psum[j * NH + wid] = es;
            S[(O_CW >> 2) + wid] = es;
            S[(O_CS2 >> 2) + wid] = s2;
        }
    }
    __syncthreads();

    {
        const int ct = wid;
        float dC[4] = {0.f, 0.f, 0.f, 0.f};
        uint32_t aA = smb + O_MSM + ((((lg >> 1) << 3) + lr) * 264 + ct * 16 + (lg & 1) * 8) * 2;
        uint32_t bA = smb + O_WH + ((lane & 7) * 136 + ((lane >> 3) & 1) * 8) * 2;
        #pragma unroll
        for (int kk = 0; kk < 8; kk++) {
            int r = kk * 16;
            uint32_t a[4], bb[2];
            ldmx4t(a, aA + r * 528);
            ldmx2(bb, bA + r * 2);
            mma16816(dC, a, bb[0], bb[1]);
        }
        int c = ct * 16 + (lane >> 2), h0 = (lane & 3) * 2;
        float g1 = S[(O_GIP >> 2) + c],     e1 = S[(O_BEI >> 2) + c];
        float g2 = S[(O_GIP >> 2) + c + 8], e2 = S[(O_BEI >> 2) + c + 8];
        float s20 = S[(O_CS2 >> 2) + h0], s21 = S[(O_CS2 >> 2) + h0 + 1];
        float W0 = S[(O_CW >> 2) + h0],  W1 = S[(O_CW >> 2) + h0 + 1];
        float* pc = g_pctx + (size_t)j * (NH * C_);
        pc[h0 * 256 + c]           = g1 * (dC[0] - s20) + e1 * W0;
        pc[(h0 + 1) * 256 + c]     = g1 * (dC[1] - s21) + e1 * W1;
        pc[h0 * 256 + c + 8]       = g2 * (dC[2] - s20) + e2 * W0;
        pc[(h0 + 1) * 256 + c + 8] = g2 * (dC[3] - s21) + e2 * W1;
    }
}

// ---- K2a: softmax-combine + L2 prefetch of k2b weights ----
__global__ void k2a(const float* __restrict__ W_kv, const float* __restrict__ W1w,
                    const float* __restrict__ W2w) {
    __shared__ float pm[128], ps[128], ef[128], red[4], red2[4], cacc[4 * 256];
    const int b = blockIdx.x >> 3, h = blockIdx.x & 7;
    const int t = threadIdx.x, lane = t & 31;
    const int col = t & 255, sl = t >> 8;

    // ---- L2 warm: each of 128 blocks loads a 256-float4 slice of each weight ----
    {
        int idx = blockIdx.x * 256 + col;           // covers 32768 float4 per array
        if (sl == 0) {
            float4 a = ((const float4*)W1w)[idx];
            float4 bb = ((const float4*)W2w)[idx];
            float4 c = ((const float4*)W_kv)[idx];
            float s = a.x + bb.x + c.x;
            if (s != s) g_pref[0] = s;              // never taken for finite inputs
        }
    }

    if (t < 128) {
        pm[t] = g_pmax[(b * 128 + t) * NH + h];
        ps[t] = g_psum[(b * 128 + t) * NH + h];
    }
    __syncthreads();
    if (t < 128) {
        float v = pm[t];
        #pragma unroll
        for (int o = 16; o >= 1; o >>= 1) v = fmaxf(v, __shfl_xor_sync(~0u, v, o));
        if (lane == 0) red[t >> 5] = v;
    }
    __syncthreads();
    float gmax = fmaxf(fmaxf(red[0], red[1]), fmaxf(red[2], red[3]));
    if (t < 128) ef[t] = __expf(pm[t] - gmax);
    __syncthreads();
    if (t < 128) {
        float v = ps[t] * ef[t];
        #pragma unroll
        for (int o = 16; o >= 1; o >>= 1) v += __shfl_xor_sync(~0u, v, o);
        if (lane == 0) red2[t >> 5] = v;
    }
    __syncthreads();
    float acc = 0.f;
    const float* p = g_pctx + ((size_t)(b * 128 + sl * 32) * NH + h) * C_ + col;
    #pragma unroll 4
    for (int ch = 0; ch < 32; ch++)
        acc += ef[sl * 32 + ch] * p[(size_t)ch * NH * C_];
    cacc[sl * 256 + col] = acc;
    __syncthreads();
    if (sl == 0) {
        float inv = 1.f / (red2[0] + red2[1] + red2[2] + red2[3]);
        float tot = cacc[col] + cacc[256 + col] + cacc[512 + col] + cacc[768 + col];
        g_ctxn[(b * NH + h) * C_ + col] = tot * inv;
    }
}

// ---- K2b: V-proj + residual + LN + FFN, 1024 threads with k-split ----
__global__ void __launch_bounds__(1024) k2b(
    const float* __restrict__ query, const float* __restrict__ W_kv,
    const float* __restrict__ b_kv, const float* __restrict__ g_f,
    const float* __restrict__ be_f, const float* __restrict__ W1,
    const float* __restrict__ b1, const float* __restrict__ W2,
    const float* __restrict__ b2, float* __restrict__ out) {
    __shared__ float ctxn[NH * C_], xs[C_], hs[C_], us[FFN], part[1024], red[8], red2[8];
    const int b = blockIdx.x, t = threadIdx.x, lane = t & 31, wid = t >> 5;
    for (int i = t; i < NH * C_; i += 1024) ctxn[i] = g_ctxn[b * NH * C_ + i];
    __syncthreads();
    {
        const int tt = t & 255, sl = t >> 8;
        const int h = tt >> 5;
        const float* W = W_kv + C_ + tt;
        const float* cx = ctxn + h * C_ + sl * 64;
        float a0 = 0.f, a1 = 0.f, a2 = 0.f, a3 = 0.f;
        #pragma unroll 4
        for (int c = 0; c < 64; c += 4) {
            a0 += cx[c] * W[(size_t)(sl * 64 + c) * (2 * C_)];
            a1 += cx[c + 1] * W[(size_t)(sl * 64 + c + 1) * (2 * C_)];
            a2 += cx[c + 2] * W[(size_t)(sl * 64 + c + 2) * (2 * C_)];
            a3 += cx[c + 3] * W[(size_t)(sl * 64 + c + 3) * (2 * C_)];
        }
        part[sl * 256 + tt] = (a0 + a1) + (a2 + a3);
    }
    __syncthreads();
    if (t < C_) {
        float x = b_kv[C_ + t] + ((part[t] + part[256 + t]) + (part[512 + t] + part[768 + t]))
                + query[b * C_ + t];
        xs[t] = x;
        float s = x, s2 = x * x;
        #pragma unroll
        for (int o = 16; o >= 1; o >>= 1) {
            s += __shfl_xor_sync(~0u, s, o);
            s2 += __shfl_xor_sync(~0u, s2, o);
        }
        if (lane == 0) { red[wid] = s; red2[wid] = s2; }
    }
    __syncthreads();
    if (t < C_) {
        float su = 0.f, sq = 0.f;
        #pragma unroll
        for (int i = 0; i < 8; i++) { su += red[i]; sq += red2[i]; }
        float mean = su / C_, var = sq / C_ - mean * mean, rs = rsqrtf(var + EPS);
        hs[t] = (xs[t] - mean) * rs * g_f[t] + be_f[t];
    }
    __syncthreads();
    {
        const int f = t & 511, sl = t >> 9;
        const float* W = W1 + f;
        const int c0 = sl * 128;
        float a0 = 0.f, a1 = 0.f, a2 = 0.f, a3 = 0.f;
        #pragma unroll 4
        for (int c = 0; c < 128; c += 4) {
            a0 += hs[c0 + c] * W[(size_t)(c0 + c) * FFN];
            a1 += hs[c0 + c + 1] * W[(size_t)(c0 + c + 1) * FFN];
            a2 += hs[c0 + c + 2] * W[(size_t)(c0 + c + 2) * FFN];
            a3 += hs[c0 + c + 3] * W[(size_t)(c0 + c + 3) * FFN];
        }
        part[sl * 512 + f] = (a0 + a1) + (a2 + a3);
    }
    __syncthreads();
    if (t < FFN) {
        float u = b1[t] + part[t] + part[512 + t];
        us[t] = 0.5f * u * (1.f + erff(u * 0.70710678118654752f));
    }
    __syncthreads();
    {
        const int tt = t & 255, sl = t >> 8;
        const float* W = W2 + tt;
        const int f0 = sl * 128;
        float a0 = 0.f, a1 = 0.f, a2 = 0.f, a3 = 0.f;
        #pragma unroll 4
        for (int f = 0; f < 128; f += 4) {
            a0 += us[f0 + f] * W[(size_t)(f0 + f) * C_];
            a1 += us[f0 + f + 1] * W[(size_t)(f0 + f + 1) * C_];
            a2 += us[f0 + f + 2] * W[(size_t)(f0 + f + 2) * C_];
            a3 += us[f0 + f + 3] * W[(size_t)(f0 + f + 3) * C_];
        }
        part[sl * 256 + tt] = (a0 + a1) + (a2 + a3);
    }
    __syncthreads();
    if (t < C_)
        out[b * C_ + t] = xs[t] + b2[t]
            + ((part[t] + part[256 + t]) + (part[512 + t] + part[768 + t]));
}

extern "C" void kernel_launch(void* const* d_in, const int* in_sizes, int n_in,
                              void* d_out, int out_size) {
    const float* query = (const float*)d_in[0];
    const float* mem   = (const float*)d_in[1];
    const float* ior   = (const float*)d_in[2];
    const float* W_ip  = (const float*)d_in[3];
    const float* b_ip  = (const float*)d_in[4];
    const float* g_ip  = (const float*)d_in[5];
    const float* be_ip = (const float*)d_in[6];
    const float* W_q   = (const float*)d_in[7];
    const float* b_q   = (const float*)d_in[8];
    const float* W_kv  = (const float*)d_in[9];
    const float* b_kv  = (const float*)d_in[10];
    const float* g_q   = (const float*)d_in[11];
    const float* be_q  = (const float*)d_in[12];
    const float* g_f   = (const float*)d_in[13];
    const float* be_f  = (const float*)d_in[14];
    const float* W1    = (const float*)d_in[15];
    const float* b1    = (const float*)d_in[16];
    const float* W2    = (const float*)d_in[17];
    const float* b2    = (const float*)d_in[18];

    cudaFuncSetAttribute(k1, cudaFuncAttributeMaxDynamicSharedMemorySize, SM1);
    k0f<<<B_ + 64, 1024>>>(query, W_q, b_q, W_kv, b_kv, g_q, be_q, g_ip, be_ip, W_ip);
    k1<<<JOBS, 512, SM1>>>(mem, ior, b_ip, g_ip, be_ip);
    k2a<<<B_ * NH, 1024>>>(W_kv, W1, W2);
    k2b<<<B_, 1024>>>(query, W_kv, b_kv, g_f, be_f, W1, b1, W2, b2, (float*)d_out);
}

// round 16
// speedup vs baseline: 1.3749x; 1.3749x over previous
#include <cuda_runtime.h>
#include <cuda_fp16.h>
#include <cstdint>
#include <cstddef>

#define B_ 16
#define L_ 16384
#define C_ 256
#define NH 8
#define FFN 512
#define EPS 1e-5f
#define SCALE_ATT 0.17677669529663687f
#define JOBS 2048

// k1 smem byte offsets
#define O_A   0         /* A fp16 double buffer: 2 x 10240 */
#define O_B   20480     /* B fp16 quad buffer: 4 x 20480 -> 102400 */
#define O_MSM 0         /* m^ fp16 [128][264] = 67584, overlays GEMM bufs */
#define O_SPC 102400    /* score partials [4][128][8] = 16384 */
#define O_ST  118784    /* row sum partials [128][4] = 2048 */
#define O_QS  120832    /* row sumsq partials [128][4] = 2048 */
#define O_WH  122880    /* w~ fp16 [8][136] = 2176 */
#define O_GQ  125056    /* gq fp16 [8][264] = 4224 */
#define O_IOR 129280    /* [8][128] float = 4096 */
#define O_SC  133376    /* scores float [8][128] = 4096 */
#define O_MU  137472    /* 128 floats */
#define O_RS  137984    /* 128 floats */
#define O_CG  138496
#define O_CQC 138528
#define O_CS2 138560
#define O_CW  138592
#define O_BIP 138624
#define O_GIP 139648
#define O_BEI 140672
#define SM1   141696

__device__ __half g_gqh[B_ * NH * C_];
__device__ float g_G[B_ * NH];
__device__ float g_qc[B_ * NH];
__device__ float g_pmax[JOBS * NH];
__device__ float g_psum[JOBS * NH];
__device__ float g_pctx[(size_t)JOBS * NH * C_];
__device__ float g_ctxn[B_ * NH * C_];
__device__ __align__(16) __half g_wh[C_ * C_];   // W_ip^T fp16, n-major

__device__ __forceinline__ uint32_t smem_u32(const void* p) {
    uint32_t a;
    asm("{ .reg .u64 t; cvta.to.shared.u64 t, %1; cvt.u32.u64 %0, t; }" : "=r"(a) : "l"(p));
    return a;
}
__device__ __forceinline__ void ldmx4(uint32_t* r, uint32_t a) {
    asm volatile("ldmatrix.sync.aligned.m8n8.x4.shared.b16 {%0,%1,%2,%3}, [%4];"
        : "=r"(r[0]), "=r"(r[1]), "=r"(r[2]), "=r"(r[3]) : "r"(a));
}
__device__ __forceinline__ void ldmx4t(uint32_t* r, uint32_t a) {
    asm volatile("ldmatrix.sync.aligned.m8n8.x4.trans.shared.b16 {%0,%1,%2,%3}, [%4];"
        : "=r"(r[0]), "=r"(r[1]), "=r"(r[2]), "=r"(r[3]) : "r"(a));
}
__device__ __forceinline__ void ldmx2(uint32_t* r, uint32_t a) {
    asm volatile("ldmatrix.sync.aligned.m8n8.x2.shared.b16 {%0,%1}, [%2];"
        : "=r"(r[0]), "=r"(r[1]) : "r"(a));
}
__device__ __forceinline__ void mma16816(float* d, const uint32_t* a, uint32_t b0, uint32_t b1) {
    asm volatile("mma.sync.aligned.m16n8k16.row.col.f32.f16.f16.f32 "
        "{%0,%1,%2,%3}, {%4,%5,%6,%7}, {%8,%9}, {%0,%1,%2,%3};"
        : "+f"(d[0]), "+f"(d[1]), "+f"(d[2]), "+f"(d[3])
        : "r"(a[0]), "r"(a[1]), "r"(a[2]), "r"(a[3]), "r"(b0), "r"(b1));
}
#define CPA(dst, src) asm volatile("cp.async.cg.shared.global [%0], [%1], 16;" :: "r"(dst), "l"(src))
#define CPC() asm volatile("cp.async.commit_group;" ::: "memory")
#define CPW(n) asm volatile("cp.async.wait_group %0;" :: "n"(n) : "memory")

// ---- K0 fused: blocks 0-15 = query fold; blocks 16-79 = W_ip^T transpose ----
__global__ void __launch_bounds__(1024) k0f(
    const float* __restrict__ query, const float* __restrict__ W_q,
    const float* __restrict__ b_q, const float* __restrict__ W_kv,
    const float* __restrict__ b_kv, const float* __restrict__ g_q,
    const float* __restrict__ be_q, const float* __restrict__ g_ip,
    const float* __restrict__ be_ip, const float* __restrict__ W_ip) {
    const int t = threadIdx.x, lane = t & 31, wid = t >> 5;

    if (blockIdx.x >= B_) {   // ---- transpose W_ip -> g_wh fp16 ----
        __shared__ float tile[32][33];
        const int bi = blockIdx.x - B_;
        const int bx = bi & 7, by = bi >> 3;
        const int tx = lane, ty = wid;
        tile[ty][tx] = W_ip[(by * 32 + ty) * C_ + bx * 32 + tx];
        __syncthreads();
        g_wh[(bx * 32 + ty) * C_ + by * 32 + tx] = __float2half_rn(tile[tx][ty]);
        return;
    }

    __shared__ float qn[C_], qs[C_], part[4 * C_], red[8], red2[8];
    __shared__ float wG[32 * 8], wQ[32 * 8];
    const int b = blockIdx.x;

    if (t < C_) {
        float x = query[b * C_ + t];
        float s = x, s2 = x * x;
        #pragma unroll
        for (int o = 16; o >= 1; o >>= 1) {
            s += __shfl_xor_sync(~0u, s, o);
            s2 += __shfl_xor_sync(~0u, s2, o);
        }
        if (lane == 0) { red[wid] = s; red2[wid] = s2; }
    }
    __syncthreads();
    if (t < C_) {
        float su = 0.f, sq = 0.f;
        #pragma unroll
        for (int i = 0; i < 8; i++) { su += red[i]; sq += red2[i]; }
        float mean = su / C_, var = sq / C_ - mean * mean, rs = rsqrtf(var + EPS);
        qn[t] = (query[b * C_ + t] - mean) * rs * g_q[t] + be_q[t];
    }
    __syncthreads();
    {
        const int tt = t & 255, sl = t >> 8;
        const float* W = W_q + tt;
        float a0 = 0.f, a1 = 0.f, a2 = 0.f, a3 = 0.f;
        const int c0 = sl * 64;
        #pragma unroll 4
        for (int c = 0; c < 64; c += 4) {
            a0 += qn[c0 + c] * W[(size_t)(c0 + c) * C_];
            a1 += qn[c0 + c + 1] * W[(size_t)(c0 + c + 1) * C_];
            a2 += qn[c0 + c + 2] * W[(size_t)(c0 + c + 2) * C_];
            a3 += qn[c0 + c + 3] * W[(size_t)(c0 + c + 3) * C_];
        }
        part[sl * C_ + tt] = (a0 + a1) + (a2 + a3);
    }
    __syncthreads();
    if (t < C_)
        qs[t] = b_q[t] + ((part[t] + part[C_ + t]) + (part[2 * C_ + t] + part[3 * C_ + t]));
    __syncthreads();
    {
        float gAcc = 0.f, qAcc = 0.f;
        for (int i = 0; i < 8; i++) {
            const int c = wid * 8 + i;
            const float* wr = W_kv + (size_t)c * (2 * C_);
            float accs[8];
            #pragma unroll
            for (int h = 0; h < NH; h++)
                accs[h] = wr[h * 32 + lane] * qs[h * 32 + lane];
            #pragma unroll
            for (int h = 0; h < NH; h++) {
                float v = accs[h];
                #pragma unroll
                for (int o = 16; o >= 1; o >>= 1) v += __shfl_xor_sync(~0u, v, o);
                if (lane == h) {
                    float a = v * SCALE_ATT;
                    __half gh = __float2half_rn(a * g_ip[c]);
                    g_gqh[(b * NH + h) * C_ + c] = gh;
                    gAcc += __half2float(gh);
                    qAcc += a * be_ip[c];
                }
            }
        }
        if (lane < NH) { wG[wid * 8 + lane] = gAcc; wQ[wid * 8 + lane] = qAcc; }
    }
    __syncthreads();
    if (t < NH) {
        float G = 0.f, Q = 0.f;
        #pragma unroll 8
        for (int w = 0; w < 32; w++) { G += wG[w * 8 + t]; Q += wQ[w * 8 + t]; }
        float qb = 0.f;
        #pragma unroll 8
        for (int d = 0; d < 32; d++) qb += qs[t * 32 + d] * b_kv[t * 32 + d];
        g_G[b * NH + t] = G;
        g_qc[b * NH + t] = Q + qb * SCALE_ATT;
    }
}

// ---- K1: fp16 HMMA fused kernel; score MMA fed from accum registers ----
__global__ void __launch_bounds__(512, 1)
k1(const float* __restrict__ mem, const float* __restrict__ ior,
   const float* __restrict__ b_ip, const float* __restrict__ g_ip,
   const float* __restrict__ be_ip) {
    extern __shared__ char sm[];
    float* S = (float*)sm;
    const uint32_t smb = smem_u32(sm);
    const int t = threadIdx.x, lane = t & 31, wid = t >> 5;
    const int rg = wid >> 2, cg = wid & 3;    // 4x4 warp grid
    const int j = blockIdx.x, b = j >> 7, row0 = (j & 127) << 7;

    for (int i = t; i < NH * C_; i += 512)
        *(__half*)(sm + O_GQ + (((i >> 8) * 264 + (i & 255)) * 2)) = g_gqh[b * NH * C_ + i];
    if (t < NH) {
        S[(O_CG >> 2) + t] = g_G[b * NH + t];
        S[(O_CQC >> 2) + t] = g_qc[b * NH + t];
    }
    for (int i = t; i < NH * 128; i += 512)
        S[(O_IOR >> 2) + i] = ior[(size_t)(b * NH + (i >> 7)) * L_ + row0 + (i & 127)];
    if (t < C_) {
        S[(O_BIP >> 2) + t] = b_ip[t];
        S[(O_GIP >> 2) + t] = g_ip[t];
        S[(O_BEI >> 2) + t] = be_ip[t];
    }

    const float4* mem4 = (const float4*)mem;
    const int ar = t >> 2, aq = t & 3;
    const size_t abase = (size_t)(b * L_ + row0 + ar) * 64;
    float4 av0 = mem4[abase + aq * 2], av1 = mem4[abase + aq * 2 + 1];

    const int bn = t >> 1, bf = t & 1;
    #pragma unroll
    for (int pk = 0; pk < 2; pk++) {
        const char* sH = (const char*)g_wh + ((size_t)bn * 256 + pk * 32 + bf * 16) * 2;
        uint32_t d0 = smb + O_B + pk * 20480 + bn * 80 + bf * 32;
        CPA(d0, sH); CPA(d0 + 16, sH + 16);
        CPC();
    }

    float d[16][4];
    #pragma unroll
    for (int i = 0; i < 16; i++)
        #pragma unroll
        for (int q = 0; q < 4; q++) d[i][q] = 0.f;

    const int lg = lane >> 3, lr = lane & 7;
    const uint32_t aOff = (rg * 32 + ((lg & 1) << 3) + lr) * 80 + (lg >> 1) * 16;
    const uint32_t bOff = (cg * 64 + ((lg >> 1) << 3) + lr) * 80 + (lg & 1) * 16;

    for (int kc = 0; kc < 8; kc++) {
        {
            __half2 h0 = __floats2half2_rn(av0.x, av0.y);
            __half2 h1 = __floats2half2_rn(av0.z, av0.w);
            __half2 h2 = __floats2half2_rn(av1.x, av1.y);
            __half2 h3 = __floats2half2_rn(av1.z, av1.w);
            *(uint4*)(sm + O_A + (kc & 1) * 10240 + ar * 80 + aq * 16) =
                make_uint4(*(uint32_t*)&h0, *(uint32_t*)&h1, *(uint32_t*)&h2, *(uint32_t*)&h3);
        }
        if (kc < 7) {
            av0 = mem4[abase + (kc + 1) * 8 + aq * 2];
            av1 = mem4[abase + (kc + 1) * 8 + aq * 2 + 1];
        }
        if (kc < 6) {
            const char* sH = (const char*)g_wh + ((size_t)bn * 256 + (kc + 2) * 32 + bf * 16) * 2;
            uint32_t d0 = smb + O_B + ((kc + 2) & 3) * 20480 + bn * 80 + bf * 32;
            CPA(d0, sH); CPA(d0 + 16, sH + 16);
            CPC();
            CPW(2);
        } else if (kc == 6) {
            CPW(1);
        } else {
            CPW(0);
        }
        __syncthreads();

        const uint32_t aAddr = smb + O_A + (kc & 1) * 10240 + aOff;
        const uint32_t bufB = smb + O_B + (kc & 3) * 20480 + bOff;
        #pragma unroll
        for (int ks = 0; ks < 2; ks++) {
            uint32_t a[2][4];
            ldmx4(a[0], aAddr + ks * 32);
            ldmx4(a[1], aAddr + 1280 + ks * 32);
            uint32_t bh[4][4];
            #pragma unroll
            for (int jt = 0; jt < 4; jt++)
                ldmx4(bh[jt], bufB + jt * 1280 + ks * 32);
            #pragma unroll
            for (int mi = 0; mi < 2; mi++)
                #pragma unroll
                for (int jt = 0; jt < 4; jt++) {
                    mma16816(d[mi * 8 + 2 * jt], a[mi], bh[jt][0], bh[jt][1]);
                    mma16816(d[mi * 8 + 2 * jt + 1], a[mi], bh[jt][2], bh[jt][3]);
                }
        }
    }
    __syncthreads();

    // ---- pass 1: bias+relu, row stats, msm write, keep fp16 A-frags in regs ----
    const int cq = (lane & 3) * 2;
    uint32_t af[2][4][4];
    #pragma unroll
    for (int mi = 0; mi < 2; mi++) {
        int rA = rg * 32 + mi * 16 + (lane >> 2), rB = rA + 8;
        float sA = 0.f, qA = 0.f, sB = 0.f, qB = 0.f;
        #pragma unroll
        for (int nj = 0; nj < 8; nj++) {
            int c = cg * 64 + (nj >> 1) * 16 + (nj & 1) * 8 + cq;
            float2 bb = *(float2*)&S[(O_BIP >> 2) + c];
            float* dd = d[mi * 8 + nj];
            float x0 = fmaxf(dd[0] + bb.x, 0.f), x1 = fmaxf(dd[1] + bb.y, 0.f);
            float y0 = fmaxf(dd[2] + bb.x, 0.f), y1 = fmaxf(dd[3] + bb.y, 0.f);
            sA += x0 + x1; qA += x0 * x0 + x1 * x1;
            sB += y0 + y1; qB += y0 * y0 + y1 * y1;
            __half2 hA = __floats2half2_rn(x0, x1);
            __half2 hB = __floats2half2_rn(y0, y1);
            *(__half2*)(sm + O_MSM + (rA * 264 + c) * 2) = hA;
            *(__half2*)(sm + O_MSM + (rB * 264 + c) * 2) = hB;
            af[mi][nj >> 1][(nj & 1) * 2]     = *(uint32_t*)&hA;
            af[mi][nj >> 1][(nj & 1) * 2 + 1] = *(uint32_t*)&hB;
        }
        #pragma unroll
        for (int o = 1; o <= 2; o <<= 1) {
            sA += __shfl_xor_sync(~0u, sA, o); qA += __shfl_xor_sync(~0u, qA, o);
            sB += __shfl_xor_sync(~0u, sB, o); qB += __shfl_xor_sync(~0u, qB, o);
        }
        if ((lane & 3) == 0) {
            S[(O_ST >> 2) + rA * 4 + cg] = sA; S[(O_QS >> 2) + rA * 4 + cg] = qA;
            S[(O_ST >> 2) + rB * 4 + cg] = sB; S[(O_QS >> 2) + rB * 4 + cg] = qB;
        }
    }

    // ---- score MMA from registers: P partial over this warp's 64-col k-slice ----
    {
        float dS[2][4] = {{0.f, 0.f, 0.f, 0.f}, {0.f, 0.f, 0.f, 0.f}};
        const uint32_t bA = smb + O_GQ + ((lane & 7) * 264 + ((lane >> 3) & 1) * 8) * 2;
        #pragma unroll
        for (int tt = 0; tt < 4; tt++) {
            uint32_t bb[2];
            ldmx2(bb, bA + (cg * 64 + tt * 16) * 2);
            mma16816(dS[0], af[0][tt], bb[0], bb[1]);
            mma16816(dS[1], af[1][tt], bb[0], bb[1]);
        }
        #pragma unroll
        for (int mi = 0; mi < 2; mi++) {
            int r = rg * 32 + mi * 16 + (lane >> 2), h0 = (lane & 3) * 2;
            *(float2*)&S[(O_SPC >> 2) + cg * 1024 + r * 8 + h0] =
                make_float2(dS[mi][0], dS[mi][1]);
            *(float2*)&S[(O_SPC >> 2) + cg * 1024 + (r + 8) * 8 + h0] =
                make_float2(dS[mi][2], dS[mi][3]);
        }
    }
    __syncthreads();

    // ---- score combine: sc = (rs*(P - mu*G) + QC) * ior ----
    for (int e = t; e < NH * 128; e += 512) {
        int h = e >> 7, rr = e & 127;
        float P = (S[(O_SPC >> 2) + rr * 8 + h] + S[(O_SPC >> 2) + 1024 + rr * 8 + h])
                + (S[(O_SPC >> 2) + 2048 + rr * 8 + h] + S[(O_SPC >> 2) + 3072 + rr * 8 + h]);
        const float* st = S + (O_ST >> 2) + rr * 4;
        const float* sqp = S + (O_QS >> 2) + rr * 4;
        float su = (st[0] + st[1]) + (st[2] + st[3]);
        float sq = (sqp[0] + sqp[1]) + (sqp[2] + sqp[3]);
        float mu = su * (1.f / C_);
        float rs = rsqrtf(sq * (1.f / C_) - mu * mu + EPS);
        if (h == 0) { S[(O_MU >> 2) + rr] = mu; S[(O_RS >> 2) + rr] = rs; }
        S[(O_SC >> 2) + e] = (rs * (P - mu * S[(O_CG >> 2) + h]) + S[(O_CQC >> 2) + h])
                             * S[(O_IOR >> 2) + e];
    }
    __syncthreads();

    // ---- per-tile softmax; w~ = e*rs fp16; W, s2 per head ----
    if (wid < NH) {
        float v0 = S[(O_SC >> 2) + wid * 128 + lane];
        float v1 = S[(O_SC >> 2) + wid * 128 + 32 + lane];
        float v2 = S[(O_SC >> 2) + wid * 128 + 64 + lane];
        float v3 = S[(O_SC >> 2) + wid * 128 + 96 + lane];
        float mx = fmaxf(fmaxf(v0, v1), fmaxf(v2, v3));
        #pragma unroll
        for (int o = 16; o >= 1; o >>= 1) mx = fmaxf(mx, __shfl_xor_sync(~0u, mx, o));
        float e0 = __expf(v0 - mx), e1 = __expf(v1 - mx);
        float e2 = __expf(v2 - mx), e3 = __expf(v3 - mx);
        float rs0 = S[(O_RS >> 2) + lane],      mu0 = S[(O_MU >> 2) + lane];
        float rs1 = S[(O_RS >> 2) + 32 + lane], mu1 = S[(O_MU >> 2) + 32 + lane];
        float rs2 = S[(O_RS >> 2) + 64 + lane], mu2 = S[(O_MU >> 2) + 64 + lane];
        float rs3 = S[(O_RS >> 2) + 96 + lane], mu3 = S[(O_MU >> 2) + 96 + lane];
        float w0 = e0 * rs0, w1 = e1 * rs1, w2 = e2 * rs2, w3 = e3 * rs3;
        *(__half*)(sm + O_WH + (wid * 136 + lane) * 2) = __float2half_rn(w0);
        *(__half*)(sm + O_WH + (wid * 136 + 32 + lane) * 2) = __float2half_rn(w1);
        *(__half*)(sm + O_WH + (wid * 136 + 64 + lane) * 2) = __float2half_rn(w2);
        *(__half*)(sm + O_WH + (wid * 136 + 96 + lane) * 2) = __float2half_rn(w3);
        float es = (e0 + e1) + (e2 + e3);
        float s2 = w0 * mu0 + w1 * mu1 + w2 * mu2 + w3 * mu3;
        #pragma unroll
        for (int o = 16; o >= 1; o >>= 1) {
            es += __shfl_xor_sync(~0u, es, o);
            s2 += __shfl_xor_sync(~0u, s2, o);
        }
        if (lane == 0) {
            g_pmax[j * NH + wid] = mx;
            g_psum[j * NH + wid] = es;
            S[(O_CW >> 2) + wid] = es;
            S[(O_CS2 >> 2) + wid] = s2;
        }
    }
    __syncthreads();

    // ---- ctx MMA: ctxT[256,8] = msm^T @ w~^T; LN-fold; write pctx ----
    {
        const int ct = wid;
        float dC[4] = {0.f, 0.f, 0.f, 0.f};
        uint32_t aA = smb + O_MSM + ((((lg >> 1) << 3) + lr) * 264 + ct * 16 + (lg & 1) * 8) * 2;
        uint32_t bA = smb + O_WH + ((lane & 7) * 136 + ((lane >> 3) & 1) * 8) * 2;
        #pragma unroll
        for (int kk = 0; kk < 8; kk++) {
            int r = kk * 16;
            uint32_t a[4], bb[2];
            ldmx4t(a, aA + r * 528);
            ldmx2(bb, bA + r * 2);
            mma16816(dC, a, bb[0], bb[1]);
        }
        int c = ct * 16 + (lane >> 2), h0 = (lane & 3) * 2;
        float g1 = S[(O_GIP >> 2) + c],     e1 = S[(O_BEI >> 2) + c];
        float g2 = S[(O_GIP >> 2) + c + 8], e2 = S[(O_BEI >> 2) + c + 8];
        float s20 = S[(O_CS2 >> 2) + h0], s21 = S[(O_CS2 >> 2) + h0 + 1];
        float W0 = S[(O_CW >> 2) + h0],  W1 = S[(O_CW >> 2) + h0 + 1];
        float* pc = g_pctx + (size_t)j * (NH * C_);
        pc[h0 * 256 + c]           = g1 * (dC[0] - s20) + e1 * W0;
        pc[(h0 + 1) * 256 + c]     = g1 * (dC[1] - s21) + e1 * W1;
        pc[h0 * 256 + c + 8]       = g2 * (dC[2] - s20) + e2 * W0;
        pc[(h0 + 1) * 256 + c + 8] = g2 * (dC[3] - s21) + e2 * W1;
    }
}

// ---- K2a: parallel softmax-combine of 128 partials, one block per (b,h) ----
__global__ void k2a() {
    __shared__ float pm[128], ps[128], ef[128], red[4], red2[4], cacc[4 * 256];
    const int b = blockIdx.x >> 3, h = blockIdx.x & 7;
    const int t = threadIdx.x, lane = t & 31;
    const int col = t & 255, sl = t >> 8;
    if (t < 128) {
        pm[t] = g_pmax[(b * 128 + t) * NH + h];
        ps[t] = g_psum[(b * 128 + t) * NH + h];
    }
    __syncthreads();
    if (t < 128) {
        float v = pm[t];
        #pragma unroll
        for (int o = 16; o >= 1; o >>= 1) v = fmaxf(v, __shfl_xor_sync(~0u, v, o));
        if (lane == 0) red[t >> 5] = v;
    }
    __syncthreads();
    float gmax = fmaxf(fmaxf(red[0], red[1]), fmaxf(red[2], red[3]));
    if (t < 128) ef[t] = __expf(pm[t] - gmax);
    __syncthreads();
    if (t < 128) {
        float v = ps[t] * ef[t];
        #pragma unroll
        for (int o = 16; o >= 1; o >>= 1) v += __shfl_xor_sync(~0u, v, o);
        if (lane == 0) red2[t >> 5] = v;
    }
    __syncthreads();
    float acc = 0.f;
    const float* p = g_pctx + ((size_t)(b * 128 + sl * 32) * NH + h) * C_ + col;
    #pragma unroll 4
    for (int ch = 0; ch < 32; ch++)
        acc += ef[sl * 32 + ch] * p[(size_t)ch * NH * C_];
    cacc[sl * 256 + col] = acc;
    __syncthreads();
    if (sl == 0) {
        float inv = 1.f / (red2[0] + red2[1] + red2[2] + red2[3]);
        float tot = cacc[col] + cacc[256 + col] + cacc[512 + col] + cacc[768 + col];
        g_ctxn[(b * NH + h) * C_ + col] = tot * inv;
    }
}

// ---- K2b: V-proj + residual + LN + FFN, 1024 threads with k-split ----
__global__ void __launch_bounds__(1024) k2b(
    const float* __restrict__ query, const float* __restrict__ W_kv,
    const float* __restrict__ b_kv, const float* __restrict__ g_f,
    const float* __restrict__ be_f, const float* __restrict__ W1,
    const float* __restrict__ b1, const float* __restrict__ W2,
    const float* __restrict__ b2, float* __restrict__ out) {
    __shared__ float ctxn[NH * C_], xs[C_], hs[C_], us[FFN], part[1024], red[8], red2[8];
    const int b = blockIdx.x, t = threadIdx.x, lane = t & 31, wid = t >> 5;
    for (int i = t; i < NH * C_; i += 1024) ctxn[i] = g_ctxn[b * NH * C_ + i];
    __syncthreads();
    {
        const int tt = t & 255, sl = t >> 8;
        const int h = tt >> 5;
        const float* W = W_kv + C_ + tt;
        const float* cx = ctxn + h * C_ + sl * 64;
        float a0 = 0.f, a1 = 0.f, a2 = 0.f, a3 = 0.f;
        #pragma unroll 4
        for (int c = 0; c < 64; c += 4) {
            a0 += cx[c] * W[(size_t)(sl * 64 + c) * (2 * C_)];
            a1 += cx[c + 1] * W[(size_t)(sl * 64 + c + 1) * (2 * C_)];
            a2 += cx[c + 2] * W[(size_t)(sl * 64 + c + 2) * (2 * C_)];
            a3 += cx[c + 3] * W[(size_t)(sl * 64 + c + 3) * (2 * C_)];
        }
        part[sl * 256 + tt] = (a0 + a1) + (a2 + a3);
    }
    __syncthreads();
    if (t < C_) {
        float x = b_kv[C_ + t] + ((part[t] + part[256 + t]) + (part[512 + t] + part[768 + t]))
                + query[b * C_ + t];
        xs[t] = x;
        float s = x, s2 = x * x;
        #pragma unroll
        for (int o = 16; o >= 1; o >>= 1) {
            s += __shfl_xor_sync(~0u, s, o);
            s2 += __shfl_xor_sync(~0u, s2, o);
        }
        if (lane == 0) { red[wid] = s; red2[wid] = s2; }
    }
    __syncthreads();
    if (t < C_) {
        float su = 0.f, sq = 0.f;
        #pragma unroll
        for (int i = 0; i < 8; i++) { su += red[i]; sq += red2[i]; }
        float mean = su / C_, var = sq / C_ - mean * mean, rs = rsqrtf(var + EPS);
        hs[t] = (xs[t] - mean) * rs * g_f[t] + be_f[t];
    }
    __syncthreads();
    {
        const int f = t & 511, sl = t >> 9;
        const float* W = W1 + f;
        const int c0 = sl * 128;
        float a0 = 0.f, a1 = 0.f, a2 = 0.f, a3 = 0.f;
        #pragma unroll 4
        for (int c = 0; c < 128; c += 4) {
            a0 += hs[c0 + c] * W[(size_t)(c0 + c) * FFN];
            a1 += hs[c0 + c + 1] * W[(size_t)(c0 + c + 1) * FFN];
            a2 += hs[c0 + c + 2] * W[(size_t)(c0 + c + 2) * FFN];
            a3 += hs[c0 + c + 3] * W[(size_t)(c0 + c + 3) * FFN];
        }
        part[sl * 512 + f] = (a0 + a1) + (a2 + a3);
    }
    __syncthreads();
    if (t < FFN) {
        float u = b1[t] + part[t] + part[512 + t];
        us[t] = 0.5f * u * (1.f + erff(u * 0.70710678118654752f));
    }
    __syncthreads();
    {
        const int tt = t & 255, sl = t >> 8;
        const float* W = W2 + tt;
        const int f0 = sl * 128;
        float a0 = 0.f, a1 = 0.f, a2 = 0.f, a3 = 0.f;
        #pragma unroll 4
        for (int f = 0; f < 128; f += 4) {
            a0 += us[f0 + f] * W[(size_t)(f0 + f) * C_];
            a1 += us[f0 + f + 1] * W[(size_t)(f0 + f + 1) * C_];
            a2 += us[f0 + f + 2] * W[(size_t)(f0 + f + 2) * C_];
            a3 += us[f0 + f + 3] * W[(size_t)(f0 + f + 3) * C_];
        }
        part[sl * 256 + tt] = (a0 + a1) + (a2 + a3);
    }
    __syncthreads();
    if (t < C_)
        out[b * C_ + t] = xs[t] + b2[t]
            + ((part[t] + part[256 + t]) + (part[512 + t] + part[768 + t]));
}

extern "C" void kernel_launch(void* const* d_in, const int* in_sizes, int n_in,
                              void* d_out, int out_size) {
    const float* query = (const float*)d_in[0];
    const float* mem   = (const float*)d_in[1];
    const float* ior   = (const float*)d_in[2];
    const float* W_ip  = (const float*)d_in[3];
    const float* b_ip  = (const float*)d_in[4];
    const float* g_ip  = (const float*)d_in[5];
    const float* be_ip = (const float*)d_in[6];
    const float* W_q   = (const float*)d_in[7];
    const float* b_q   = (const float*)d_in[8];
    const float* W_kv  = (const float*)d_in[9];
    const float* b_kv  = (const float*)d_in[10];
    const float* g_q   = (const float*)d_in[11];
    const float* be_q  = (const float*)d_in[12];
    const float* g_f   = (const float*)d_in[13];
    const float* be_f  = (const float*)d_in[14];
    const float* W1    = (const float*)d_in[15];
    const float* b1    = (const float*)d_in[16];
    const float* W2    = (const float*)d_in[17];
    const float* b2    = (const float*)d_in[18];

    cudaFuncSetAttribute(k1, cudaFuncAttributeMaxDynamicSharedMemorySize, SM1);
    k0f<<<B_ + 64, 1024>>>(query, W_q, b_q, W_kv, b_kv, g_q, be_q, g_ip, be_ip, W_ip);
    k1<<<JOBS, 512, SM1>>>(mem, ior, b_ip, g_ip, be_ip);
    k2a<<<B_ * NH, 1024>>>();
    k2b<<<B_, 1024>>>(query, W_kv, b_kv, g_f, be_f, W1, b1, W2, b2, (float*)d_out);
}

// round 17
// speedup vs baseline: 1.3997x; 1.0180x over previous
#include <cuda_runtime.h>
#include <cuda_fp16.h>
#include <cstdint>
#include <cstddef>

#define B_ 16
#define L_ 16384
#define C_ 256
#define NH 8
#define FFN 512
#define EPS 1e-5f
#define SCALE_ATT 0.17677669529663687f
#define JOBS 2048

// k1 smem byte offsets
#define O_A   0         /* A fp16 double buffer: 2 x 10240 */
#define O_B   20480     /* B fp16 quad buffer: 4 x 20480 -> 102400 */
#define O_CTP 0         /* ctx partials [4][256][8] f32 = 32768, reuses GEMM bufs */
#define O_SPC 102400    /* score partials [4][128][8] = 16384 */
#define O_ST  118784    /* row sum partials [128][4] = 2048 */
#define O_QS  120832    /* row sumsq partials [128][4] = 2048 */
#define O_WH  122880    /* w~ fp16 [8][136] = 2176 */
#define O_GQ  125056    /* gq fp16 [8][264] = 4224 */
#define O_IOR 129280    /* [8][128] float = 4096 */
#define O_SC  133376    /* scores float [8][128] = 4096 */
#define O_MU  137472    /* 128 floats */
#define O_RS  137984    /* 128 floats */
#define O_CG  138496
#define O_CQC 138528
#define O_CS2 138560
#define O_CW  138592
#define O_BIP 138624
#define O_GIP 139648
#define O_BEI 140672
#define SM1   141696

__device__ __half g_gqh[B_ * NH * C_];
__device__ float g_G[B_ * NH];
__device__ float g_qc[B_ * NH];
__device__ float g_pmax[JOBS * NH];
__device__ float g_psum[JOBS * NH];
__device__ float g_pctx[(size_t)JOBS * NH * C_];
__device__ float g_ctxn[B_ * NH * C_];
__device__ __align__(16) __half g_wh[C_ * C_];   // W_ip^T fp16, n-major

__device__ __forceinline__ uint32_t smem_u32(const void* p) {
    uint32_t a;
    asm("{ .reg .u64 t; cvta.to.shared.u64 t, %1; cvt.u32.u64 %0, t; }" : "=r"(a) : "l"(p));
    return a;
}
__device__ __forceinline__ void ldmx4(uint32_t* r, uint32_t a) {
    asm volatile("ldmatrix.sync.aligned.m8n8.x4.shared.b16 {%0,%1,%2,%3}, [%4];"
        : "=r"(r[0]), "=r"(r[1]), "=r"(r[2]), "=r"(r[3]) : "r"(a));
}
__device__ __forceinline__ void ldmx2(uint32_t* r, uint32_t a) {
    asm volatile("ldmatrix.sync.aligned.m8n8.x2.shared.b16 {%0,%1}, [%2];"
        : "=r"(r[0]), "=r"(r[1]) : "r"(a));
}
__device__ __forceinline__ uint32_t movm(uint32_t s) {
    uint32_t d;
    asm volatile("movmatrix.sync.aligned.m8n8.trans.b16 %0, %1;" : "=r"(d) : "r"(s));
    return d;
}
__device__ __forceinline__ void mma16816(float* d, const uint32_t* a, uint32_t b0, uint32_t b1) {
    asm volatile("mma.sync.aligned.m16n8k16.row.col.f32.f16.f16.f32 "
        "{%0,%1,%2,%3}, {%4,%5,%6,%7}, {%8,%9}, {%0,%1,%2,%3};"
        : "+f"(d[0]), "+f"(d[1]), "+f"(d[2]), "+f"(d[3])
        : "r"(a[0]), "r"(a[1]), "r"(a[2]), "r"(a[3]), "r"(b0), "r"(b1));
}
#define CPA(dst, src) asm volatile("cp.async.cg.shared.global [%0], [%1], 16;" :: "r"(dst), "l"(src))
#define CPC() asm volatile("cp.async.commit_group;" ::: "memory")
#define CPW(n) asm volatile("cp.async.wait_group %0;" :: "n"(n) : "memory")

// ---- K0 fused: blocks 0-15 = query fold; blocks 16-79 = W_ip^T transpose ----
__global__ void __launch_bounds__(1024) k0f(
    const float* __restrict__ query, const float* __restrict__ W_q,
    const float* __restrict__ b_q, const float* __restrict__ W_kv,
    const float* __restrict__ b_kv, const float* __restrict__ g_q,
    const float* __restrict__ be_q, const float* __restrict__ g_ip,
    const float* __restrict__ be_ip, const float* __restrict__ W_ip) {
    const int t = threadIdx.x, lane = t & 31, wid = t >> 5;

    if (blockIdx.x >= B_) {
        __shared__ float tile[32][33];
        const int bi = blockIdx.x - B_;
        const int bx = bi & 7, by = bi >> 3;
        const int tx = lane, ty = wid;
        tile[ty][tx] = W_ip[(by * 32 + ty) * C_ + bx * 32 + tx];
        __syncthreads();
        g_wh[(bx * 32 + ty) * C_ + by * 32 + tx] = __float2half_rn(tile[tx][ty]);
        return;
    }

    __shared__ float qn[C_], qs[C_], part[4 * C_], red[8], red2[8];
    __shared__ float wG[32 * 8], wQ[32 * 8];
    const int b = blockIdx.x;

    if (t < C_) {
        float x = query[b * C_ + t];
        float s = x, s2 = x * x;
        #pragma unroll
        for (int o = 16; o >= 1; o >>= 1) {
            s += __shfl_xor_sync(~0u, s, o);
            s2 += __shfl_xor_sync(~0u, s2, o);
        }
        if (lane == 0) { red[wid] = s; red2[wid] = s2; }
    }
    __syncthreads();
    if (t < C_) {
        float su = 0.f, sq = 0.f;
        #pragma unroll
        for (int i = 0; i < 8; i++) { su += red[i]; sq += red2[i]; }
        float mean = su / C_, var = sq / C_ - mean * mean, rs = rsqrtf(var + EPS);
        qn[t] = (query[b * C_ + t] - mean) * rs * g_q[t] + be_q[t];
    }
    __syncthreads();
    {
        const int tt = t & 255, sl = t >> 8;
        const float* W = W_q + tt;
        float a0 = 0.f, a1 = 0.f, a2 = 0.f, a3 = 0.f;
        const int c0 = sl * 64;
        #pragma unroll 4
        for (int c = 0; c < 64; c += 4) {
            a0 += qn[c0 + c] * W[(size_t)(c0 + c) * C_];
            a1 += qn[c0 + c + 1] * W[(size_t)(c0 + c + 1) * C_];
            a2 += qn[c0 + c + 2] * W[(size_t)(c0 + c + 2) * C_];
            a3 += qn[c0 + c + 3] * W[(size_t)(c0 + c + 3) * C_];
        }
        part[sl * C_ + tt] = (a0 + a1) + (a2 + a3);
    }
    __syncthreads();
    if (t < C_)
        qs[t] = b_q[t] + ((part[t] + part[C_ + t]) + (part[2 * C_ + t] + part[3 * C_ + t]));
    __syncthreads();
    {
        float gAcc = 0.f, qAcc = 0.f;
        for (int i = 0; i < 8; i++) {
            const int c = wid * 8 + i;
            const float* wr = W_kv + (size_t)c * (2 * C_);
            float accs[8];
            #pragma unroll
            for (int h = 0; h < NH; h++)
                accs[h] = wr[h * 32 + lane] * qs[h * 32 + lane];
            #pragma unroll
            for (int h = 0; h < NH; h++) {
                float v = accs[h];
                #pragma unroll
                for (int o = 16; o >= 1; o >>= 1) v += __shfl_xor_sync(~0u, v, o);
                if (lane == h) {
                    float a = v * SCALE_ATT;
                    __half gh = __float2half_rn(a * g_ip[c]);
                    g_gqh[(b * NH + h) * C_ + c] = gh;
                    gAcc += __half2float(gh);
                    qAcc += a * be_ip[c];
                }
            }
        }
        if (lane < NH) { wG[wid * 8 + lane] = gAcc; wQ[wid * 8 + lane] = qAcc; }
    }
    __syncthreads();
    if (t < NH) {
        float G = 0.f, Q = 0.f;
        #pragma unroll 8
        for (int w = 0; w < 32; w++) { G += wG[w * 8 + t]; Q += wQ[w * 8 + t]; }
        float qb = 0.f;
        #pragma unroll 8
        for (int d = 0; d < 32; d++) qb += qs[t * 32 + d] * b_kv[t * 32 + d];
        g_G[b * NH + t] = G;
        g_qc[b * NH + t] = Q + qb * SCALE_ATT;
    }
}

// ---- K1: fp16 HMMA fused kernel; score AND ctx MMAs fed from registers ----
__global__ void __launch_bounds__(512, 1)
k1(const float* __restrict__ mem, const float* __restrict__ ior,
   const float* __restrict__ b_ip, const float* __restrict__ g_ip,
   const float* __restrict__ be_ip) {
    extern __shared__ char sm[];
    float* S = (float*)sm;
    const uint32_t smb = smem_u32(sm);
    const int t = threadIdx.x, lane = t & 31, wid = t >> 5;
    const int rg = wid >> 2, cg = wid & 3;    // 4x4 warp grid
    const int j = blockIdx.x, b = j >> 7, row0 = (j & 127) << 7;

    for (int i = t; i < NH * C_; i += 512)
        *(__half*)(sm + O_GQ + (((i >> 8) * 264 + (i & 255)) * 2)) = g_gqh[b * NH * C_ + i];
    if (t < NH) {
        S[(O_CG >> 2) + t] = g_G[b * NH + t];
        S[(O_CQC >> 2) + t] = g_qc[b * NH + t];
    }
    for (int i = t; i < NH * 128; i += 512)
        S[(O_IOR >> 2) + i] = ior[(size_t)(b * NH + (i >> 7)) * L_ + row0 + (i & 127)];
    if (t < C_) {
        S[(O_BIP >> 2) + t] = b_ip[t];
        S[(O_GIP >> 2) + t] = g_ip[t];
        S[(O_BEI >> 2) + t] = be_ip[t];
    }

    const float4* mem4 = (const float4*)mem;
    const int ar = t >> 2, aq = t & 3;
    const size_t abase = (size_t)(b * L_ + row0 + ar) * 64;
    float4 av0 = mem4[abase + aq * 2], av1 = mem4[abase + aq * 2 + 1];

    const int bn = t >> 1, bf = t & 1;
    #pragma unroll
    for (int pk = 0; pk < 2; pk++) {
        const char* sH = (const char*)g_wh + ((size_t)bn * 256 + pk * 32 + bf * 16) * 2;
        uint32_t d0 = smb + O_B + pk * 20480 + bn * 80 + bf * 32;
        CPA(d0, sH); CPA(d0 + 16, sH + 16);
        CPC();
    }

    float d[16][4];
    #pragma unroll
    for (int i = 0; i < 16; i++)
        #pragma unroll
        for (int q = 0; q < 4; q++) d[i][q] = 0.f;

    const int lg = lane >> 3, lr = lane & 7;
    const uint32_t aOff = (rg * 32 + ((lg & 1) << 3) + lr) * 80 + (lg >> 1) * 16;
    const uint32_t bOff = (cg * 64 + ((lg >> 1) << 3) + lr) * 80 + (lg & 1) * 16;

    for (int kc = 0; kc < 8; kc++) {
        {
            __half2 h0 = __floats2half2_rn(av0.x, av0.y);
            __half2 h1 = __floats2half2_rn(av0.z, av0.w);
            __half2 h2 = __floats2half2_rn(av1.x, av1.y);
            __half2 h3 = __floats2half2_rn(av1.z, av1.w);
            *(uint4*)(sm + O_A + (kc & 1) * 10240 + ar * 80 + aq * 16) =
                make_uint4(*(uint32_t*)&h0, *(uint32_t*)&h1, *(uint32_t*)&h2, *(uint32_t*)&h3);
        }
        if (kc < 7) {
            av0 = mem4[abase + (kc + 1) * 8 + aq * 2];
            av1 = mem4[abase + (kc + 1) * 8 + aq * 2 + 1];
        }
        if (kc < 6) {
            const char* sH = (const char*)g_wh + ((size_t)bn * 256 + (kc + 2) * 32 + bf * 16) * 2;
            uint32_t d0 = smb + O_B + ((kc + 2) & 3) * 20480 + bn * 80 + bf * 32;
            CPA(d0, sH); CPA(d0 + 16, sH + 16);
            CPC();
            CPW(2);
        } else if (kc == 6) {
            CPW(1);
        } else {
            CPW(0);
        }
        __syncthreads();

        const uint32_t aAddr = smb + O_A + (kc & 1) * 10240 + aOff;
        const uint32_t bufB = smb + O_B + (kc & 3) * 20480 + bOff;
        #pragma unroll
        for (int ks = 0; ks < 2; ks++) {
            uint32_t a[2][4];
            ldmx4(a[0], aAddr + ks * 32);
            ldmx4(a[1], aAddr + 1280 + ks * 32);
            uint32_t bh[4][4];
            #pragma unroll
            for (int jt = 0; jt < 4; jt++)
                ldmx4(bh[jt], bufB + jt * 1280 + ks * 32);
            #pragma unroll
            for (int mi = 0; mi < 2; mi++)
                #pragma unroll
                for (int jt = 0; jt < 4; jt++) {
                    mma16816(d[mi * 8 + 2 * jt], a[mi], bh[jt][0], bh[jt][1]);
                    mma16816(d[mi * 8 + 2 * jt + 1], a[mi], bh[jt][2], bh[jt][3]);
                }
        }
    }
    __syncthreads();

    // ---- pass 1: bias+relu, row stats; keep fp16 A-frags in regs (no msm) ----
    const int cq = (lane & 3) * 2;
    uint32_t af[2][4][4];
    #pragma unroll
    for (int mi = 0; mi < 2; mi++) {
        int rA = rg * 32 + mi * 16 + (lane >> 2), rB = rA + 8;
        float sA = 0.f, qA = 0.f, sB = 0.f, qB = 0.f;
        #pragma unroll
        for (int nj = 0; nj < 8; nj++) {
            int c = cg * 64 + (nj >> 1) * 16 + (nj & 1) * 8 + cq;
            float2 bb = *(float2*)&S[(O_BIP >> 2) + c];
            float* dd = d[mi * 8 + nj];
            float x0 = fmaxf(dd[0] + bb.x, 0.f), x1 = fmaxf(dd[1] + bb.y, 0.f);
            float y0 = fmaxf(dd[2] + bb.x, 0.f), y1 = fmaxf(dd[3] + bb.y, 0.f);
            sA += x0 + x1; qA += x0 * x0 + x1 * x1;
            sB += y0 + y1; qB += y0 * y0 + y1 * y1;
            __half2 hA = __floats2half2_rn(x0, x1);
            __half2 hB = __floats2half2_rn(y0, y1);
            af[mi][nj >> 1][(nj & 1) * 2]     = *(uint32_t*)&hA;
            af[mi][nj >> 1][(nj & 1) * 2 + 1] = *(uint32_t*)&hB;
        }
        #pragma unroll
        for (int o = 1; o <= 2; o <<= 1) {
            sA += __shfl_xor_sync(~0u, sA, o); qA += __shfl_xor_sync(~0u, qA, o);
            sB += __shfl_xor_sync(~0u, sB, o); qB += __shfl_xor_sync(~0u, qB, o);
        }
        if ((lane & 3) == 0) {
            S[(O_ST >> 2) + rA * 4 + cg] = sA; S[(O_QS >> 2) + rA * 4 + cg] = qA;
            S[(O_ST >> 2) + rB * 4 + cg] = sB; S[(O_QS >> 2) + rB * 4 + cg] = qB;
        }
    }

    // ---- score MMA from registers: P partial over this warp's 64-col k-slice ----
    {
        float dS[2][4] = {{0.f, 0.f, 0.f, 0.f}, {0.f, 0.f, 0.f, 0.f}};
        const uint32_t bA = smb + O_GQ + ((lane & 7) * 264 + ((lane >> 3) & 1) * 8) * 2;
        #pragma unroll
        for (int tt = 0; tt < 4; tt++) {
            uint32_t bb[2];
            ldmx2(bb, bA + (cg * 64 + tt * 16) * 2);
            mma16816(dS[0], af[0][tt], bb[0], bb[1]);
            mma16816(dS[1], af[1][tt], bb[0], bb[1]);
        }
        #pragma unroll
        for (int mi = 0; mi < 2; mi++) {
            int r = rg * 32 + mi * 16 + (lane >> 2), h0 = (lane & 3) * 2;
            *(float2*)&S[(O_SPC >> 2) + cg * 1024 + r * 8 + h0] =
                make_float2(dS[mi][0], dS[mi][1]);
            *(float2*)&S[(O_SPC >> 2) + cg * 1024 + (r + 8) * 8 + h0] =
                make_float2(dS[mi][2], dS[mi][3]);
        }
    }
    __syncthreads();

    // ---- score combine: sc = (rs*(P - mu*G) + QC) * ior ----
    for (int e = t; e < NH * 128; e += 512) {
        int h = e >> 7, rr = e & 127;
        float P = (S[(O_SPC >> 2) + rr * 8 + h] + S[(O_SPC >> 2) + 1024 + rr * 8 + h])
                + (S[(O_SPC >> 2) + 2048 + rr * 8 + h] + S[(O_SPC >> 2) + 3072 + rr * 8 + h]);
        const float* st = S + (O_ST >> 2) + rr * 4;
        const float* sqp = S + (O_QS >> 2) + rr * 4;
        float su = (st[0] + st[1]) + (st[2] + st[3]);
        float sq = (sqp[0] + sqp[1]) + (sqp[2] + sqp[3]);
        float mu = su * (1.f / C_);
        float rs = rsqrtf(sq * (1.f / C_) - mu * mu + EPS);
        if (h == 0) { S[(O_MU >> 2) + rr] = mu; S[(O_RS >> 2) + rr] = rs; }
        S[(O_SC >> 2) + e] = (rs * (P - mu * S[(O_CG >> 2) + h]) + S[(O_CQC >> 2) + h])
                             * S[(O_IOR >> 2) + e];
    }
    __syncthreads();

    // ---- per-tile softmax; w~ = e*rs fp16; W, s2 per head ----
    if (wid < NH) {
        float v0 = S[(O_SC >> 2) + wid * 128 + lane];
        float v1 = S[(O_SC >> 2) + wid * 128 + 32 + lane];
        float v2 = S[(O_SC >> 2) + wid * 128 + 64 + lane];
        float v3 = S[(O_SC >> 2) + wid * 128 + 96 + lane];
        float mx = fmaxf(fmaxf(v0, v1), fmaxf(v2, v3));
        #pragma unroll
        for (int o = 16; o >= 1; o >>= 1) mx = fmaxf(mx, __shfl_xor_sync(~0u, mx, o));
        float e0 = __expf(v0 - mx), e1 = __expf(v1 - mx);
        float e2 = __expf(v2 - mx), e3 = __expf(v3 - mx);
        float rs0 = S[(O_RS >> 2) + lane],      mu0 = S[(O_MU >> 2) + lane];
        float rs1 = S[(O_RS >> 2) + 32 + lane], mu1 = S[(O_MU >> 2) + 32 + lane];
        float rs2 = S[(O_RS >> 2) + 64 + lane], mu2 = S[(O_MU >> 2) + 64 + lane];
        float rs3 = S[(O_RS >> 2) + 96 + lane], mu3 = S[(O_MU >> 2) + 96 + lane];
        float w0 = e0 * rs0, w1 = e1 * rs1, w2 = e2 * rs2, w3 = e3 * rs3;
        *(__half*)(sm + O_WH + (wid * 136 + lane) * 2) = __float2half_rn(w0);
        *(__half*)(sm + O_WH + (wid * 136 + 32 + lane) * 2) = __float2half_rn(w1);
        *(__half*)(sm + O_WH + (wid * 136 + 64 + lane) * 2) = __float2half_rn(w2);
        *(__half*)(sm + O_WH + (wid * 136 + 96 + lane) * 2) = __float2half_rn(w3);
        float es = (e0 + e1) + (e2 + e3);
        float s2 = w0 * mu0 + w1 * mu1 + w2 * mu2 + w3 * mu3;
        #pragma unroll
        for (int o = 16; o >= 1; o >>= 1) {
            es += __shfl_xor_sync(~0u, es, o);
            s2 += __shfl_xor_sync(~0u, s2, o);
        }
        if (lane == 0) {
            g_pmax[j * NH + wid] = mx;
            g_psum[j * NH + wid] = es;
            S[(O_CW >> 2) + wid] = es;
            S[(O_CS2 >> 2) + wid] = s2;
        }
    }
    __syncthreads();

    // ---- ctx MMA from registers via movmatrix: per-warp partials ----
    {
        const uint32_t bA = smb + O_WH + ((lane & 7) * 136 + ((lane >> 3) & 1) * 8) * 2;
        float dC[4][4];
        #pragma unroll
        for (int tt = 0; tt < 4; tt++)
            #pragma unroll
            for (int q = 0; q < 4; q++) dC[tt][q] = 0.f;
        #pragma unroll
        for (int mi = 0; mi < 2; mi++) {
            uint32_t bb[2];
            ldmx2(bb, bA + (rg * 32 + mi * 16) * 2);
            #pragma unroll
            for (int tt = 0; tt < 4; tt++) {
                uint32_t ap[4];
                ap[0] = movm(af[mi][tt][0]);
                ap[1] = movm(af[mi][tt][2]);
                ap[2] = movm(af[mi][tt][1]);
                ap[3] = movm(af[mi][tt][3]);
                mma16816(dC[tt], ap, bb[0], bb[1]);
            }
        }
        // store partials: [rg][256 c][8 h] f32 at O_CTP
        #pragma unroll
        for (int tt = 0; tt < 4; tt++) {
            int c = cg * 64 + tt * 16 + (lane >> 2), h0 = (lane & 3) * 2;
            *(float2*)&S[(O_CTP >> 2) + (rg * 256 + c) * 8 + h0] =
                make_float2(dC[tt][0], dC[tt][1]);
            *(float2*)&S[(O_CTP >> 2) + (rg * 256 + c + 8) * 8 + h0] =
                make_float2(dC[tt][2], dC[tt][3]);
        }
    }
    __syncthreads();

    // ---- reduce 4 rg partials, apply LN-fold, write pctx ----
    {
        float* pc = g_pctx + (size_t)j * (NH * C_);
        #pragma unroll
        for (int e = t; e < 2048; e += 512) {
            int c = e >> 3, h = e & 7;
            float v = (S[(O_CTP >> 2) + e] + S[(O_CTP >> 2) + 2048 + e])
                    + (S[(O_CTP >> 2) + 4096 + e] + S[(O_CTP >> 2) + 6144 + e]);
            pc[h * 256 + c] = S[(O_GIP >> 2) + c] * (v - S[(O_CS2 >> 2) + h])
                            + S[(O_BEI >> 2) + c] * S[(O_CW >> 2) + h];
        }
    }
}

// ---- K2a: parallel softmax-combine of 128 partials, one block per (b,h) ----
__global__ void k2a() {
    __shared__ float pm[128], ps[128], ef[128], red[4], red2[4], cacc[4 * 256];
    const int b = blockIdx.x >> 3, h = blockIdx.x & 7;
    const int t = threadIdx.x, lane = t & 31;
    const int col = t & 255, sl = t >> 8;
    if (t < 128) {
        pm[t] = g_pmax[(b * 128 + t) * NH + h];
        ps[t] = g_psum[(b * 128 + t) * NH + h];
    }
    __syncthreads();
    if (t < 128) {
        float v = pm[t];
        #pragma unroll
        for (int o = 16; o >= 1; o >>= 1) v = fmaxf(v, __shfl_xor_sync(~0u, v, o));
        if (lane == 0) red[t >> 5] = v;
    }
    __syncthreads();
    float gmax = fmaxf(fmaxf(red[0], red[1]), fmaxf(red[2], red[3]));
    if (t < 128) ef[t] = __expf(pm[t] - gmax);
    __syncthreads();
    if (t < 128) {
        float v = ps[t] * ef[t];
        #pragma unroll
        for (int o = 16; o >= 1; o >>= 1) v += __shfl_xor_sync(~0u, v, o);
        if (lane == 0) red2[t >> 5] = v;
    }
    __syncthreads();
    float acc = 0.f;
    const float* p = g_pctx + ((size_t)(b * 128 + sl * 32) * NH + h) * C_ + col;
    #pragma unroll 4
    for (int ch = 0; ch < 32; ch++)
        acc += ef[sl * 32 + ch] * p[(size_t)ch * NH * C_];
    cacc[sl * 256 + col] = acc;
    __syncthreads();
    if (sl == 0) {
        float inv = 1.f / (red2[0] + red2[1] + red2[2] + red2[3]);
        float tot = cacc[col] + cacc[256 + col] + cacc[512 + col] + cacc[768 + col];
        g_ctxn[(b * NH + h) * C_ + col] = tot * inv;
    }
}

// ---- K2b: V-proj + residual + LN + FFN, 1024 threads with k-split ----
__global__ void __launch_bounds__(1024) k2b(
    const float* __restrict__ query, const float* __restrict__ W_kv,
    const float* __restrict__ b_kv, const float* __restrict__ g_f,
    const float* __restrict__ be_f, const float* __restrict__ W1,
    const float* __restrict__ b1, const float* __restrict__ W2,
    const float* __restrict__ b2, float* __restrict__ out) {
    __shared__ float ctxn[NH * C_], xs[C_], hs[C_], us[FFN], part[1024], red[8], red2[8];
    const int b = blockIdx.x, t = threadIdx.x, lane = t & 31, wid = t >> 5;
    for (int i = t; i < NH * C_; i += 1024) ctxn[i] = g_ctxn[b * NH * C_ + i];
    __syncthreads();
    {
        const int tt = t & 255, sl = t >> 8;
        const int h = tt >> 5;
        const float* W = W_kv + C_ + tt;
        const float* cx = ctxn + h * C_ + sl * 64;
        float a0 = 0.f, a1 = 0.f, a2 = 0.f, a3 = 0.f;
        #pragma unroll 4
        for (int c = 0; c < 64; c += 4) {
            a0 += cx[c] * W[(size_t)(sl * 64 + c) * (2 * C_)];
            a1 += cx[c + 1] * W[(size_t)(sl * 64 + c + 1) * (2 * C_)];
            a2 += cx[c + 2] * W[(size_t)(sl * 64 + c + 2) * (2 * C_)];
            a3 += cx[c + 3] * W[(size_t)(sl * 64 + c + 3) * (2 * C_)];
        }
        part[sl * 256 + tt] = (a0 + a1) + (a2 + a3);
    }
    __syncthreads();
    if (t < C_) {
        float x = b_kv[C_ + t] + ((part[t] + part[256 + t]) + (part[512 + t] + part[768 + t]))
                + query[b * C_ + t];
        xs[t] = x;
        float s = x, s2 = x * x;
        #pragma unroll
        for (int o = 16; o >= 1; o >>= 1) {
            s += __shfl_xor_sync(~0u, s, o);
            s2 += __shfl_xor_sync(~0u, s2, o);
        }
        if (lane == 0) { red[wid] = s; red2[wid] = s2; }
    }
    __syncthreads();
    if (t < C_) {
        float su = 0.f, sq = 0.f;
        #pragma unroll
        for (int i = 0; i < 8; i++) { su += red[i]; sq += red2[i]; }
        float mean = su / C_, var = sq / C_ - mean * mean, rs = rsqrtf(var + EPS);
        hs[t] = (xs[t] - mean) * rs * g_f[t] + be_f[t];
    }
    __syncthreads();
    {
        const int f = t & 511, sl = t >> 9;
        const float* W = W1 + f;
        const int c0 = sl * 128;
        float a0 = 0.f, a1 = 0.f, a2 = 0.f, a3 = 0.f;
        #pragma unroll 4
        for (int c = 0; c < 128; c += 4) {
            a0 += hs[c0 + c] * W[(size_t)(c0 + c) * FFN];
            a1 += hs[c0 + c + 1] * W[(size_t)(c0 + c + 1) * FFN];
            a2 += hs[c0 + c + 2] * W[(size_t)(c0 + c + 2) * FFN];
            a3 += hs[c0 + c + 3] * W[(size_t)(c0 + c + 3) * FFN];
        }
        part[sl * 512 + f] = (a0 + a1) + (a2 + a3);
    }
    __syncthreads();
    if (t < FFN) {
        float u = b1[t] + part[t] + part[512 + t];
        us[t] = 0.5f * u * (1.f + erff(u * 0.70710678118654752f));
    }
    __syncthreads();
    {
        const int tt = t & 255, sl = t >> 8;
        const float* W = W2 + tt;
        const int f0 = sl * 128;
        float a0 = 0.f, a1 = 0.f, a2 = 0.f, a3 = 0.f;
        #pragma unroll 4
        for (int f = 0; f < 128; f += 4) {
            a0 += us[f0 + f] * W[(size_t)(f0 + f) * C_];
            a1 += us[f0 + f + 1] * W[(size_t)(f0 + f + 1) * C_];
            a2 += us[f0 + f + 2] * W[(size_t)(f0 + f + 2) * C_];
            a3 += us[f0 + f + 3] * W[(size_t)(f0 + f + 3) * C_];
        }
        part[sl * 256 + tt] = (a0 + a1) + (a2 + a3);
    }
    __syncthreads();
    if (t < C_)
        out[b * C_ + t] = xs[t] + b2[t]
            + ((part[t] + part[256 + t]) + (part[512 + t] + part[768 + t]));
}

extern "C" void kernel_launch(void* const* d_in, const int* in_sizes, int n_in,
                              void* d_out, int out_size) {
    const float* query = (const float*)d_in[0];
    const float* mem   = (const float*)d_in[1];
    const float* ior   = (const float*)d_in[2];
    const float* W_ip  = (const float*)d_in[3];
    const float* b_ip  = (const float*)d_in[4];
    const float* g_ip  = (const float*)d_in[5];
    const float* be_ip = (const float*)d_in[6];
    const float* W_q   = (const float*)d_in[7];
    const float* b_q   = (const float*)d_in[8];
    const float* W_kv  = (const float*)d_in[9];
    const float* b_kv  = (const float*)d_in[10];
    const float* g_q   = (const float*)d_in[11];
    const float* be_q  = (const float*)d_in[12];
    const float* g_f   = (const float*)d_in[13];
    const float* be_f  = (const float*)d_in[14];
    const float* W1    = (const float*)d_in[15];
    const float* b1    = (const float*)d_in[16];
    const float* W2    = (const float*)d_in[17];
    const float* b2    = (const float*)d_in[18];

    cudaFuncSetAttribute(k1, cudaFuncAttributeMaxDynamicSharedMemorySize, SM1);
    k0f<<<B_ + 64, 1024>>>(query, W_q, b_q, W_kv, b_kv, g_q, be_q, g_ip, be_ip, W_ip);
    k1<<<JOBS, 512, SM1>>>(mem, ior, b_ip, g_ip, be_ip);
    k2a<<<B_ * NH, 1024>>>();
    k2b<<<B_, 1024>>>(query, W_kv, b_kv, g_f, be_f, W1, b1, W2, b2, (float*)d_out);
}